// round 4
// baseline (speedup 1.0000x reference)
#include <cuda_runtime.h>
#include <cuda_bf16.h>

// AllZeroDigitalFilter: time-varying FIR with per-sample linearly-interpolated
// frame coefficients.
//   y[b,t] = sum_{k=0..M} x[b,t-k] * c[b,t,k]
//   c[b,t,k] = (1-w)*B[b,n,k] + w*B[b,min(n+1,N-1),k],  n=t/P, w=(t%P)/P
// Computed as y = A0 + w*(A1-A0) with A0 = x-window . B[n], A1 = x-window . B[n+1].

#define TAPS         50      // FILTER_ORDER + 1
#define M_ORD        49
#define FRAME_P      80
#define FRAMES_PER_BLOCK 8
#define SAMP_PER_BLOCK   (FRAMES_PER_BLOCK * FRAME_P)   // 640
#define THREADS_PER_BLOCK (SAMP_PER_BLOCK / 4)          // 160, 4 samples/thread
#define X_TILE       (SAMP_PER_BLOCK + M_ORD)           // 689
#define COEF_ROWS    (FRAMES_PER_BLOCK + 1)             // 9

__global__ __launch_bounds__(THREADS_PER_BLOCK)
void azdf_kernel(const float* __restrict__ x,
                 const float* __restrict__ bcoef,
                 float* __restrict__ y,
                 int T, int N)
{
    __shared__ float xs[X_TILE];
    __shared__ float brow[COEF_ROWS][TAPS];

    const int bidx = blockIdx.y;
    const int t0   = blockIdx.x * SAMP_PER_BLOCK;
    const int n0   = blockIdx.x * FRAMES_PER_BLOCK;
    const int tid  = threadIdx.x;

    const float* xg = x + (size_t)bidx * T;
    const float* bg = bcoef + (size_t)bidx * N * TAPS;

    // ---- stage x tile (with left halo, zero-padded) ----
    #pragma unroll
    for (int i = tid; i < X_TILE; i += THREADS_PER_BLOCK) {
        int g = t0 - M_ORD + i;
        xs[i] = (g >= 0 && g < T) ? xg[g] : 0.0f;
    }
    // ---- stage coefficient rows n0 .. n0+8 (clamped to N-1) ----
    for (int i = tid; i < COEF_ROWS * TAPS; i += THREADS_PER_BLOCK) {
        int r = i / TAPS;
        int k = i - r * TAPS;
        int n = n0 + r;
        if (n > N - 1) n = N - 1;
        brow[r][k] = bg[(size_t)n * TAPS + k];
    }
    __syncthreads();

    // ---- compute: thread handles 4 consecutive samples within one frame ----
    const int ls = tid * 4;                 // local sample base, multiple of 4
    const int fr = ls / FRAME_P;            // frame within block (0..7)
    const int p  = ls - fr * FRAME_P;       // phase within frame (multiple of 4)

    const float* b0 = brow[fr];
    const float* b1 = brow[fr + 1];

    float a00 = 0.f, a01 = 0.f, a02 = 0.f, a03 = 0.f;   // dot with b0
    float a10 = 0.f, a11 = 0.f, a12 = 0.f, a13 = 0.f;   // dot with b1

    // sliding window: at tap k, xw_s = xs[M_ORD + ls + s - k]
    float xw0 = xs[M_ORD + ls + 0];
    float xw1 = xs[M_ORD + ls + 1];
    float xw2 = xs[M_ORD + ls + 2];
    float xw3 = xs[M_ORD + ls + 3];

    #pragma unroll
    for (int k = 0; k < TAPS; ++k) {
        const float c0 = b0[k];
        const float c1 = b1[k];
        a00 = fmaf(xw0, c0, a00);  a10 = fmaf(xw0, c1, a10);
        a01 = fmaf(xw1, c0, a01);  a11 = fmaf(xw1, c1, a11);
        a02 = fmaf(xw2, c0, a02);  a12 = fmaf(xw2, c1, a12);
        a03 = fmaf(xw3, c0, a03);  a13 = fmaf(xw3, c1, a13);
        // shift window down by one for next tap
        xw3 = xw2; xw2 = xw1; xw1 = xw0;
        xw0 = (k < TAPS - 1) ? xs[M_ORD - 1 + ls - k] : 0.0f;
    }

    const int tglob = t0 + ls;
    if (tglob + 3 < T) {
        const float invP = 1.0f / (float)FRAME_P;
        float4 r;
        float w0 = (float)(p + 0) * invP;
        float w1 = (float)(p + 1) * invP;
        float w2 = (float)(p + 2) * invP;
        float w3 = (float)(p + 3) * invP;
        r.x = fmaf(w0, a10 - a00, a00);
        r.y = fmaf(w1, a11 - a01, a01);
        r.z = fmaf(w2, a12 - a02, a02);
        r.w = fmaf(w3, a13 - a03, a03);
        *reinterpret_cast<float4*>(y + (size_t)bidx * T + tglob) = r;
    } else {
        // ragged tail (only if T not a multiple of SAMP_PER_BLOCK)
        const float invP = 1.0f / (float)FRAME_P;
        float a0[4] = {a00, a01, a02, a03};
        float a1[4] = {a10, a11, a12, a13};
        #pragma unroll
        for (int s = 0; s < 4; ++s) {
            int t = tglob + s;
            if (t < T) {
                float w = (float)(p + s) * invP;
                y[(size_t)bidx * T + t] = fmaf(w, a1[s] - a0[s], a0[s]);
            }
        }
    }
}

extern "C" void kernel_launch(void* const* d_in, const int* in_sizes, int n_in,
                              void* d_out, int out_size)
{
    const float* x = (const float*)d_in[0];   // (B, T) float32
    const float* b = (const float*)d_in[1];   // (B, N, 50) float32
    float* y = (float*)d_out;                 // (B, T) float32

    // Known problem shape: B=8, T = N*80. Derive T,N from sizes with B=8.
    const int B = 8;
    const int T = in_sizes[0] / B;
    const int N = in_sizes[1] / (B * TAPS);

    // Cover all of T (equals (N*P)/SAMP_PER_BLOCK when T = N*P).
    dim3 grid((T + SAMP_PER_BLOCK - 1) / SAMP_PER_BLOCK, B);
    azdf_kernel<<<grid, THREADS_PER_BLOCK>>>(x, b, y, T, N);
}

// round 5
// speedup vs baseline: 1.5233x; 1.5233x over previous
#include <cuda_runtime.h>
#include <cuda_bf16.h>

// AllZeroDigitalFilter: time-varying FIR, y = A0 + w*(A1-A0),
// A0 = window . B[n], A1 = window . B[n+1].
//
// R5: LDS-conflict elimination.
//  - x window consumed via aligned float4 chunks (1 LDS.128 / 4 taps,
//    stride-16B across lanes = conflict-free bandwidth) instead of per-tap
//    scalar LDS with 4-way bank conflicts.
//  - coefficients broadcast as float4 (rows padded to 52, taps 50/51 = 0).

#define TAPS         50
#define TAPS_PAD     52                     // multiple of 4, extra 2 taps are 0
#define NGROUPS      (TAPS_PAD / 4)         // 13
#define FRAME_P      80
#define FRAMES_PER_BLOCK 8
#define SAMP_PER_BLOCK   (FRAMES_PER_BLOCK * FRAME_P)   // 640
#define THREADS_PER_BLOCK (SAMP_PER_BLOCK / 4)          // 160
#define XPAD         56                     // left pad, mult of 4, >= 51+3
#define X_TILE       (SAMP_PER_BLOCK + XPAD + 8)        // 704 (mult of 4)
#define COEF_ROWS    (FRAMES_PER_BLOCK + 1)             // 9

__global__ __launch_bounds__(THREADS_PER_BLOCK)
void azdf_kernel(const float* __restrict__ x,
                 const float* __restrict__ bcoef,
                 float* __restrict__ y,
                 int T, int N)
{
    __shared__ __align__(16) float xs[X_TILE];
    __shared__ __align__(16) float brow[COEF_ROWS][TAPS_PAD];

    const int bidx = blockIdx.y;
    const int t0   = blockIdx.x * SAMP_PER_BLOCK;
    const int n0   = blockIdx.x * FRAMES_PER_BLOCK;
    const int tid  = threadIdx.x;

    const float* xg = x + (size_t)bidx * T;
    const float* bg = bcoef + (size_t)bidx * N * TAPS;

    // ---- stage x tile: xs[i] = x[t0 - XPAD + i], zero-padded ----
    #pragma unroll
    for (int i = tid; i < X_TILE; i += THREADS_PER_BLOCK) {
        int g = t0 - XPAD + i;
        xs[i] = (g >= 0 && g < T) ? xg[g] : 0.0f;
    }
    // ---- stage coeff rows n0..n0+8 (clamped), padded taps = 0 ----
    #pragma unroll
    for (int i = tid; i < COEF_ROWS * TAPS_PAD; i += THREADS_PER_BLOCK) {
        int r = i / TAPS_PAD;
        int k = i - r * TAPS_PAD;
        int n = n0 + r;
        if (n > N - 1) n = N - 1;
        brow[r][k] = (k < TAPS) ? bg[(size_t)n * TAPS + k] : 0.0f;
    }
    __syncthreads();

    const int ls = tid * 4;                 // local sample base (mult of 4)
    const int fr = ls / FRAME_P;            // frame in block (0..7)
    const int p  = ls - fr * FRAME_P;       // phase (mult of 4)

    const float4* xs4 = reinterpret_cast<const float4*>(xs);
    const float4* b0v = reinterpret_cast<const float4*>(brow[fr]);
    const float4* b1v = reinterpret_cast<const float4*>(brow[fr + 1]);

    float a0[4] = {0.f, 0.f, 0.f, 0.f};
    float a1[4] = {0.f, 0.f, 0.f, 0.f};

    // Window invariant at group g (taps k = 4g+j):
    //   needed value = xs[XPAD + ls - 4g + (s - j)],  s-j in [-3, 3]
    //   w[4 + s - j], with w[0..3] = chunk at (XPAD+ls)/4 - g - 1,
    //                      w[4..7] = chunk at (XPAD+ls)/4 - g
    const int cbase = (XPAD + ls) / 4;
    float w[8];
    {
        float4 hi = xs4[cbase];
        float4 lo = xs4[cbase - 1];
        w[0] = lo.x; w[1] = lo.y; w[2] = lo.z; w[3] = lo.w;
        w[4] = hi.x; w[5] = hi.y; w[6] = hi.z; w[7] = hi.w;
    }

    #pragma unroll
    for (int g = 0; g < NGROUPS; ++g) {
        const float4 c0 = b0v[g];
        const float4 c1 = b1v[g];
        const float c0a[4] = {c0.x, c0.y, c0.z, c0.w};
        const float c1a[4] = {c1.x, c1.y, c1.z, c1.w};

        #pragma unroll
        for (int j = 0; j < 4; ++j) {
            const float q0 = c0a[j];
            const float q1 = c1a[j];
            #pragma unroll
            for (int s = 0; s < 4; ++s) {
                const float v = w[4 + s - j];
                a0[s] = fmaf(v, q0, a0[s]);
                a1[s] = fmaf(v, q1, a1[s]);
            }
        }

        if (g < NGROUPS - 1) {
            // shift: new hi = old lo, load new lo one chunk lower
            w[4] = w[0]; w[5] = w[1]; w[6] = w[2]; w[7] = w[3];
            float4 lo = xs4[cbase - g - 2];
            w[0] = lo.x; w[1] = lo.y; w[2] = lo.z; w[3] = lo.w;
        }
    }

    // ---- blend and store ----
    const int tglob = t0 + ls;
    const float invP = 1.0f / (float)FRAME_P;
    if (tglob + 3 < T) {
        float4 r;
        r.x = fmaf((float)(p + 0) * invP, a1[0] - a0[0], a0[0]);
        r.y = fmaf((float)(p + 1) * invP, a1[1] - a0[1], a0[1]);
        r.z = fmaf((float)(p + 2) * invP, a1[2] - a0[2], a0[2]);
        r.w = fmaf((float)(p + 3) * invP, a1[3] - a0[3], a0[3]);
        *reinterpret_cast<float4*>(y + (size_t)bidx * T + tglob) = r;
    } else {
        #pragma unroll
        for (int s = 0; s < 4; ++s) {
            int t = tglob + s;
            if (t < T) {
                float ww = (float)(p + s) * invP;
                y[(size_t)bidx * T + t] = fmaf(ww, a1[s] - a0[s], a0[s]);
            }
        }
    }
}

extern "C" void kernel_launch(void* const* d_in, const int* in_sizes, int n_in,
                              void* d_out, int out_size)
{
    const float* x = (const float*)d_in[0];   // (B, T) float32
    const float* b = (const float*)d_in[1];   // (B, N, 50) float32
    float* y = (float*)d_out;                 // (B, T) float32

    const int B = 8;
    const int T = in_sizes[0] / B;
    const int N = in_sizes[1] / (B * TAPS);

    dim3 grid((T + SAMP_PER_BLOCK - 1) / SAMP_PER_BLOCK, B);
    azdf_kernel<<<grid, THREADS_PER_BLOCK>>>(x, b, y, T, N);
}

// round 10
// speedup vs baseline: 1.5265x; 1.0021x over previous
#include <cuda_runtime.h>
#include <cuda_bf16.h>

// AllZeroDigitalFilter: time-varying FIR, y = A0 + w*(A1-A0).
// R6: packed f32x2 FMA. Accumulator lane = (A0, A1) packed in 64 bits.
//   coeff pair (b[n][k], b[n+1][k]) pre-interleaved in smem -> 1 LDS.64 each,
//   x value splat to both halves, fma.rn.f32x2 does both dots at once.

#define TAPS         50
#define TAPS_PAD     52                     // multiple of 4
#define NGROUPS      (TAPS_PAD / 4)         // 13
#define FRAME_P      80
#define FRAMES_PER_BLOCK 8
#define SAMP_PER_BLOCK   (FRAMES_PER_BLOCK * FRAME_P)   // 640
#define THREADS_PER_BLOCK (SAMP_PER_BLOCK / 4)          // 160
#define XPAD         56                     // left pad, mult of 8, >= 51+3
#define X_TILE       (SAMP_PER_BLOCK + XPAD + 8)        // 704

typedef unsigned long long u64;

__device__ __forceinline__ u64 splat2(float v) {
    u64 r;
    asm("mov.b64 %0, {%1, %1};" : "=l"(r) : "f"(v));
    return r;
}
__device__ __forceinline__ void fma2(u64& acc, u64 a, u64 b) {
    asm("fma.rn.f32x2 %0, %1, %2, %0;" : "+l"(acc) : "l"(a), "l"(b));
}
__device__ __forceinline__ void unpack2(float& lo, float& hi, u64 v) {
    asm("mov.b64 {%0, %1}, %2;" : "=f"(lo), "=f"(hi) : "l"(v));
}

__global__ __launch_bounds__(THREADS_PER_BLOCK)
void azdf_kernel(const float* __restrict__ x,
                 const float* __restrict__ bcoef,
                 float* __restrict__ y,
                 int T, int N)
{
    __shared__ __align__(16) float xs[X_TILE];
    // bpair[r][k] = (b[n0+r][k], b[n0+r+1][k]) packed; rows 16B-aligned (52*8=416B)
    __shared__ __align__(16) float2 bpair[FRAMES_PER_BLOCK][TAPS_PAD];

    const int bidx = blockIdx.y;
    const int t0   = blockIdx.x * SAMP_PER_BLOCK;
    const int n0   = blockIdx.x * FRAMES_PER_BLOCK;
    const int tid  = threadIdx.x;

    const float* xg = x + (size_t)bidx * T;
    const float* bg = bcoef + (size_t)bidx * N * TAPS;

    // ---- stage x tile: xs[i] = x[t0 - XPAD + i], zero-padded ----
    if (t0 >= XPAD && t0 + (X_TILE - XPAD) <= T) {
        // interior fast path: fully in range, 16B-aligned (t0-XPAD mult of 8)
        const float4* src = reinterpret_cast<const float4*>(xg + t0 - XPAD);
        float4* dst = reinterpret_cast<float4*>(xs);
        #pragma unroll
        for (int i = tid; i < X_TILE / 4; i += THREADS_PER_BLOCK)
            dst[i] = src[i];
    } else {
        #pragma unroll
        for (int i = tid; i < X_TILE; i += THREADS_PER_BLOCK) {
            int g = t0 - XPAD + i;
            xs[i] = (g >= 0 && g < T) ? xg[g] : 0.0f;
        }
    }
    // ---- stage interleaved coeff pairs ----
    #pragma unroll
    for (int i = tid; i < FRAMES_PER_BLOCK * TAPS_PAD; i += THREADS_PER_BLOCK) {
        int r = i / TAPS_PAD;
        int k = i - r * TAPS_PAD;
        int n  = n0 + r;     if (n  > N - 1) n  = N - 1;
        int n1 = n0 + r + 1; if (n1 > N - 1) n1 = N - 1;
        float2 p;
        if (k < TAPS) {
            p.x = bg[(size_t)n  * TAPS + k];
            p.y = bg[(size_t)n1 * TAPS + k];
        } else {
            p.x = 0.0f; p.y = 0.0f;
        }
        bpair[r][k] = p;
    }
    __syncthreads();

    const int ls = tid * 4;                 // local sample base (mult of 4)
    const int fr = ls / FRAME_P;            // frame in block
    const int p  = ls - fr * FRAME_P;       // phase (mult of 4)

    const float4* xs4 = reinterpret_cast<const float4*>(xs);
    const ulonglong2* cp2 = reinterpret_cast<const ulonglong2*>(bpair[fr]);

    u64 A[4] = {0ull, 0ull, 0ull, 0ull};    // (A0, A1) per sample

    // window: at group g, taps k=4g+j need xs[XPAD + ls + s - 4g - j]
    //   = w[4 + s - j], w[0..3] = chunk (cbase-g-1), w[4..7] = chunk (cbase-g)
    const int cbase = (XPAD + ls) / 4;
    float w[8];
    {
        float4 hi = xs4[cbase];
        float4 lo = xs4[cbase - 1];
        w[0] = lo.x; w[1] = lo.y; w[2] = lo.z; w[3] = lo.w;
        w[4] = hi.x; w[5] = hi.y; w[6] = hi.z; w[7] = hi.w;
    }

    #pragma unroll
    for (int g = 0; g < NGROUPS; ++g) {
        // coeff pairs for taps 4g..4g+3 (two LDS.128 broadcasts)
        ulonglong2 cA = cp2[2 * g];         // taps 4g, 4g+1
        ulonglong2 cB = cp2[2 * g + 1];     // taps 4g+2, 4g+3
        const u64 c[4] = {cA.x, cA.y, cB.x, cB.y};

        // splat window values used this group: w[1..7]
        u64 v1 = splat2(w[1]), v2 = splat2(w[2]), v3 = splat2(w[3]);
        u64 v4 = splat2(w[4]), v5 = splat2(w[5]), v6 = splat2(w[6]);
        u64 v7 = splat2(w[7]);
        const u64 v[7] = {v1, v2, v3, v4, v5, v6, v7};  // v[i] = splat(w[i+1])

        // A[s] += w[4+s-j] * c[j]   (index into v: (4+s-j)-1 = 3+s-j)
        #pragma unroll
        for (int j = 0; j < 4; ++j) {
            #pragma unroll
            for (int s = 0; s < 4; ++s)
                fma2(A[s], v[3 + s - j], c[j]);
        }

        if (g < NGROUPS - 1) {
            w[4] = w[0]; w[5] = w[1]; w[6] = w[2]; w[7] = w[3];
            float4 lo = xs4[cbase - g - 2];
            w[0] = lo.x; w[1] = lo.y; w[2] = lo.z; w[3] = lo.w;
        }
    }

    // ---- blend and store ----
    float a0[4], a1[4];
    #pragma unroll
    for (int s = 0; s < 4; ++s) unpack2(a0[s], a1[s], A[s]);

    const int tglob = t0 + ls;
    const float invP = 1.0f / (float)FRAME_P;
    if (tglob + 3 < T) {
        float4 r;
        r.x = fmaf((float)(p + 0) * invP, a1[0] - a0[0], a0[0]);
        r.y = fmaf((float)(p + 1) * invP, a1[1] - a0[1], a0[1]);
        r.z = fmaf((float)(p + 2) * invP, a1[2] - a0[2], a0[2]);
        r.w = fmaf((float)(p + 3) * invP, a1[3] - a0[3], a0[3]);
        *reinterpret_cast<float4*>(y + (size_t)bidx * T + tglob) = r;
    } else {
        #pragma unroll
        for (int s = 0; s < 4; ++s) {
            int t = tglob + s;
            if (t < T) {
                float ww = (float)(p + s) * invP;
                y[(size_t)bidx * T + t] = fmaf(ww, a1[s] - a0[s], a0[s]);
            }
        }
    }
}

extern "C" void kernel_launch(void* const* d_in, const int* in_sizes, int n_in,
                              void* d_out, int out_size)
{
    const float* x = (const float*)d_in[0];   // (B, T) float32
    const float* b = (const float*)d_in[1];   // (B, N, 50) float32
    float* y = (float*)d_out;                 // (B, T) float32

    const int B = 8;
    const int T = in_sizes[0] / B;
    const int N = in_sizes[1] / (B * TAPS);

    dim3 grid((T + SAMP_PER_BLOCK - 1) / SAMP_PER_BLOCK, B);
    azdf_kernel<<<grid, THREADS_PER_BLOCK>>>(x, b, y, T, N);
}